// round 17
// baseline (speedup 1.0000x reference)
#include <cuda_runtime.h>
#include <cuda_bf16.h>
#include <math.h>

#define Bn 8
#define Tn 512
#define Cn 8
#define Fn 257
#define An 320
#define BF (Bn*Fn)   // 2056
#define FT 32        // f per psd block
#define TSN 6        // t splits (4x88 + 2x80) -> grid 432 = one resident wave
#define TLMAX 88
#define TC 8         // t chunk staged in smem (register-prefetch pipelined)

// ---- packed f32x2 helpers (FFMA2 path; ptxas won't auto-fuse) ----
#define PACK2(out, lo, hi) \
    asm("mov.b64 %0, {%1, %2};" : "=l"(out) : "f"(lo), "f"(hi))
#define UNPACK2(lo, hi, in) \
    asm("mov.b64 {%0, %1}, %2;" : "=f"(lo), "=f"(hi) : "l"(in))
#define FMA2(d, a, b, c) \
    asm("fma.rn.f32x2 %0, %1, %2, %3;" : "=l"(d) : "l"(a), "l"(b), "l"(c))

// ---------------- scratch (static device globals; no allocation) ----------------
__device__ float  g_part[(size_t)TSN*BF*36*4];    // unnormalized pair partials
__device__ float  g_msum_part[(size_t)TSN*BF*2];  // mask-weight sums per split
__device__ float  g_eval[Bn*Cn];                  // attention logits
__device__ float  g_feat[Bn*Cn*Fn];               // attention features (B,C,F)
__device__ float2 g_wsmat[(size_t)BF*Cn*Cn];      // numerator/trace (B,F,C,C)

// Hermitian pair tables (c<=e), 36 pairs
__constant__ unsigned char cP[36] = {0,0,0,0,0,0,0,0, 1,1,1,1,1,1,1, 2,2,2,2,2,2,
                                     3,3,3,3,3, 4,4,4,4, 5,5,5, 6,6, 7};
__constant__ unsigned char cE[36] = {0,1,2,3,4,5,6,7, 1,2,3,4,5,6,7, 2,3,4,5,6,7,
                                     3,4,5,6,7, 4,5,6,7, 5,6,7, 6,7, 7};
__device__ static constexpr int kP[36] = {0,0,0,0,0,0,0,0, 1,1,1,1,1,1,1, 2,2,2,2,2,2,
                                          3,3,3,3,3, 4,4,4,4, 5,5,5, 6,6, 7};
__device__ static constexpr int kE[36] = {0,1,2,3,4,5,6,7, 1,2,3,4,5,6,7, 2,3,4,5,6,7,
                                          3,4,5,6,7, 4,5,6,7, 5,6,7, 6,7, 7};
// pair index for (i,j) -> upper-triangle pair id
__constant__ unsigned char cpidx[64] = {
    0, 1, 2, 3, 4, 5, 6, 7,
    1, 8, 9,10,11,12,13,14,
    2, 9,15,16,17,18,19,20,
    3,10,16,21,22,23,24,25,
    4,11,17,22,26,27,28,29,
    5,12,18,23,27,30,31,32,
    6,13,19,24,28,31,33,34,
    7,14,20,25,29,32,34,35
};

// ---------------- PSD partial kernel smem ----------------
struct PsdSmem {
    float m0[FT][TLMAX + 1];              // c-mean speech weights, [f][t] rows
    float m1[FT][TLMAX + 1];
    union {
        float2 xt[TC][Cn][FT];            // staged x chunk, [t][c][f] (16 KB)
        float  stage[4][FT][36];          // cross-warp pair reduction (18.4 KB)
    } u;
};
#define PSD_SMEM_BYTES sizeof(PsdSmem)    // ~41 KB

// packed accumulators: lane0 = speech, lane1 = noise
template<int G>
__device__ __forceinline__ void psd_chunk(
    const PsdSmem* __restrict__ S, int lane, int st, int tb,
    unsigned long long (&aR)[9], unsigned long long (&aI)[9])
{
    #pragma unroll
    for (int tl = st; tl < TC; tl += 2) {
        float w0 = S->m0[lane][tb + tl];
        float w1 = S->m1[lane][tb + tl];
        unsigned long long W; PACK2(W, w0, w1);
        float2 xv[8];
        #pragma unroll
        for (int c = 0; c < 8; c++) xv[c] = S->u.xt[tl][c][lane];
        #pragma unroll
        for (int p = 0; p < 9; p++) {
            const int c = kP[G*9 + p];
            const int e = kE[G*9 + p];
            float pr = xv[c].x*xv[e].x + xv[c].y*xv[e].y;
            float pi = xv[c].y*xv[e].x - xv[c].x*xv[e].y;
            unsigned long long PR, PI;
            PACK2(PR, pr, pr);
            PACK2(PI, pi, pi);
            FMA2(aR[p], W, PR, aR[p]);
            FMA2(aI[p], W, PI, aI[p]);
        }
    }
}

// grid (9 ftiles, 6 tsplits, 8 b), 256 threads
__global__ __launch_bounds__(256) void k_psd_part(
    const float* __restrict__ dr, const float* __restrict__ di,
    const float* __restrict__ ms, const float* __restrict__ mn)
{
    extern __shared__ char raw[];
    PsdSmem* S = (PsdSmem*)raw;
    int ftile = blockIdx.x, ts = blockIdx.y, b = blockIdx.z;
    int f0 = ftile * FT;
    int nf = Fn - f0; if (nf > FT) nf = FT;
    // uneven t split: ts<4 -> 88 t's, ts>=4 -> 80 t's
    int t0  = (ts < 4) ? ts*88 : 352 + (ts - 4)*80;
    int TLb = (ts < 4) ? 88 : 80;
    int NCHb = TLb >> 3;
    int tid = threadIdx.x;
    int w = tid >> 5, lane = tid & 31;

    // ---- Phase A: mask c-means into smem, plus per-f t-sums ----
    #pragma unroll
    for (int ff = 0; ff < 4; ff++) {
        int fw = w*4 + ff;
        int fm = f0 + fw; if (fm > Fn - 1) fm = Fn - 1;   // clamped row
        size_t base = ((size_t)(b*Fn + fm))*Cn*Tn + t0;
        float tot0 = 0.f, tot1 = 0.f;
        for (int t = lane; t < TLb; t += 32) {
            float s0 = 0.f, s1 = 0.f;
            #pragma unroll
            for (int c = 0; c < 8; c++) {
                s0 += ms[base + (size_t)c*Tn + t];
                s1 += mn[base + (size_t)c*Tn + t];
            }
            s0 *= 0.125f; s1 *= 0.125f;
            S->m0[fw][t] = s0;
            S->m1[fw][t] = s1;
            tot0 += s0; tot1 += s1;
        }
        #pragma unroll
        for (int o = 16; o; o >>= 1) {
            tot0 += __shfl_xor_sync(0xffffffffu, tot0, o);
            tot1 += __shfl_xor_sync(0xffffffffu, tot1, o);
        }
        if (lane == 0 && fw < nf) {
            size_t mi = ((size_t)ts*BF + b*Fn + f0 + fw)*2;
            g_msum_part[mi + 0] = tot0;
            g_msum_part[mi + 1] = tot1;
        }
    }
    __syncthreads();

    // ---- Phase B: register-prefetch pipelined staging + pair accumulation ----
    int G4 = w >> 1, st = w & 1;
    int fx = f0 + lane; if (fx > Fn - 1) fx = Fn - 1;   // clamped x column
    bool fok = (f0 + lane < Fn);
    unsigned long long aR[9], aI[9];
    #pragma unroll
    for (int p = 0; p < 9; p++) { aR[p] = 0ull; aI[p] = 0ull; }

    // per-thread prefetch registers: chunk rows (it, c=w, f=lane)
    float rr[TC], ri[TC];
    {   // prefetch chunk 0 (unconditional clamped loads)
        #pragma unroll
        for (int it = 0; it < TC; it++) {
            size_t ga = ((size_t)((b*Tn + t0 + it))*Cn + w)*Fn + fx;
            rr[it] = dr[ga]; ri[it] = di[ga];
        }
    }

    for (int ch = 0; ch < NCHb; ch++) {
        int tb = ch * TC;
        // store prefetched regs to smem
        #pragma unroll
        for (int it = 0; it < TC; it++)
            S->u.xt[it][w][lane] = make_float2(rr[it], ri[it]);
        __syncthreads();

        // issue next chunk's LDGs; latency overlaps the compute below
        if (ch + 1 < NCHb) {
            int tbn = (ch + 1) * TC;
            #pragma unroll
            for (int it = 0; it < TC; it++) {
                size_t ga = ((size_t)((b*Tn + t0 + tbn + it))*Cn + w)*Fn + fx;
                rr[it] = dr[ga]; ri[it] = di[ga];
            }
        }

        if      (G4 == 0) psd_chunk<0>(S, lane, st, tb, aR, aI);
        else if (G4 == 1) psd_chunk<1>(S, lane, st, tb, aR, aI);
        else if (G4 == 2) psd_chunk<2>(S, lane, st, tb, aR, aI);
        else              psd_chunk<3>(S, lane, st, tb, aR, aI);
        __syncthreads();
    }

    // unpack packed accumulators to scalars
    float asr[9], asi[9], anr[9], ani[9];
    #pragma unroll
    for (int p = 0; p < 9; p++) {
        UNPACK2(asr[p], anr[p], aR[p]);
        UNPACK2(asi[p], ani[p], aI[p]);
    }

    // ---- reduce st pairs across the two warps of each group, write partials ----
    if (st == 1) {
        #pragma unroll
        for (int p = 0; p < 9; p++) {
            S->u.stage[G4][lane][p*4 + 0] = asr[p];
            S->u.stage[G4][lane][p*4 + 1] = asi[p];
            S->u.stage[G4][lane][p*4 + 2] = anr[p];
            S->u.stage[G4][lane][p*4 + 3] = ani[p];
        }
    }
    __syncthreads();
    if (st == 0 && fok) {
        size_t gp = (((size_t)ts*BF + b*Fn + f0 + lane)*36 + G4*9)*4;
        #pragma unroll
        for (int p = 0; p < 9; p++) {
            g_part[gp + p*4 + 0] = asr[p] + S->u.stage[G4][lane][p*4 + 0];
            g_part[gp + p*4 + 1] = asi[p] + S->u.stage[G4][lane][p*4 + 1];
            g_part[gp + p*4 + 2] = anr[p] + S->u.stage[G4][lane][p*4 + 2];
            g_part[gp + p*4 + 3] = ani[p] + S->u.stage[G4][lane][p*4 + 3];
        }
    }
}

// ---------------- finalize + MVDR solve, one warp per (b,f) -----------------------
// Coalesced smem staging of partials, then register build + warp-sync Gauss-Jordan.
// Writes attention feature and ws_mat = inv(N)@S / trace (u-independent).
__global__ __launch_bounds__(256) void k_final() {
    const unsigned FULL = 0xffffffffu;
    __shared__ float sp[8][144];        // summed pair partials per bf-local
    __shared__ float smsum[8][2];
    int tid = threadIdx.x;
    int bf0 = blockIdx.x * 8;

    // coalesced load + split-sum of pair partials (144 floats per bf)
    for (int idx = tid; idx < 8*144; idx += 256) {
        int bl = idx / 144, comp = idx % 144;
        size_t base = ((size_t)(bf0 + bl))*144 + comp;
        float v = 0.f;
        #pragma unroll
        for (int ts = 0; ts < TSN; ts++) v += g_part[(size_t)ts*BF*144 + base];
        sp[bl][comp] = v;
    }
    if (tid < 16) {
        int bl = tid >> 1, comp = tid & 1;
        float v = 0.f;
        #pragma unroll
        for (int ts = 0; ts < TSN; ts++)
            v += g_msum_part[((size_t)ts*BF + bf0 + bl)*2 + comp];
        smsum[bl][comp] = v;
    }
    __syncthreads();

    int w = tid >> 5;
    int bf = bf0 + w;
    int lane = tid & 31;
    int i = lane >> 2;                    // row 0..7
    int q = lane & 3;                     // col group
    int b = bf / Fn, f = bf % Fn;

    float inv0 = 1.f / (smsum[w][0] + 1e-15f);   // speech
    float inv1 = 1.f / (smsum[w][1] + 1e-15f);   // noise

    // build augmented [N | S] from smem
    float ar[4], ai[4];
    #pragma unroll
    for (int m = 0; m < 4; m++) {
        int j = q*4 + m;
        int col = (j < 8) ? j : (j - 8);
        int p = cpidx[i*8 + col];
        float sgn = (i <= col) ? 1.f : -1.f;
        float vr, vi, sc;
        if (j < 8) { vr = sp[w][p*4 + 2]; vi = sp[w][p*4 + 3]; sc = inv1; }
        else       { vr = sp[w][p*4 + 0]; vi = sp[w][p*4 + 1]; sc = inv0; }
        ar[m] = vr * sc;
        ai[m] = sgn * vi * sc;
    }

    // attention feature: |sum_{e != i} S[i][e]| / 7  (S entries live in q>=2 lanes)
    {
        float sr = 0.f, si = 0.f;
        if (q >= 2) {
            #pragma unroll
            for (int m = 0; m < 4; m++) {
                int c2 = (q - 2)*4 + m;
                if (c2 != i) { sr += ar[m]; si += ai[m]; }
            }
        }
        sr += __shfl_xor_sync(FULL, sr, 1);
        si += __shfl_xor_sync(FULL, si, 1);
        if (q == 2)
            g_feat[(b*Cn + i)*Fn + f] = sqrtf(sr*sr + si*si) * (1.0f/7.0f);
    }

    // Gauss-Jordan on [N | S]
    #pragma unroll
    for (int k = 0; k < 8; k++) {
        int psrc = (k << 2) | (k >> 2);
        float pvr = __shfl_sync(FULL, ar[k & 3], psrc);
        float pvi = __shfl_sync(FULL, ai[k & 3], psrc);
        float dd = 1.f / (pvr*pvr + pvi*pvi);
        float qr = pvr*dd, qi = -pvi*dd;
        if (i == k) {
            #pragma unroll
            for (int m = 0; m < 4; m++) {
                float trv = ar[m]*qr - ai[m]*qi;
                ai[m] = ar[m]*qi + ai[m]*qr;
                ar[m] = trv;
            }
        }
        float gr[4], gi[4];
        int rsrc = (k << 2) | q;
        #pragma unroll
        for (int m = 0; m < 4; m++) {
            gr[m] = __shfl_sync(FULL, ar[m], rsrc);
            gi[m] = __shfl_sync(FULL, ai[m], rsrc);
        }
        int fsrc = (i << 2) | (k >> 2);
        float fr = __shfl_sync(FULL, ar[k & 3], fsrc);
        float fi = __shfl_sync(FULL, ai[k & 3], fsrc);
        if (i != k) {
            #pragma unroll
            for (int m = 0; m < 4; m++) {
                ar[m] -= fr*gr[m] - fi*gi[m];
                ai[m] -= fr*gi[m] + fi*gr[m];
            }
        }
    }

    // trace of numerator
    float tr_r = 0.f, tr_i = 0.f;
    if (q == ((8 + i) >> 2)) {
        int m = (8 + i) & 3;
        tr_r = ar[m]; tr_i = ai[m];
    }
    #pragma unroll
    for (int o = 16; o; o >>= 1) {
        tr_r += __shfl_xor_sync(FULL, tr_r, o);
        tr_i += __shfl_xor_sync(FULL, tr_i, o);
    }
    tr_r += 1e-15f;
    float invd = 1.f / (tr_r*tr_r + tr_i*tr_i);

    // write ws_mat = numerator / trace
    if (q >= 2) {
        #pragma unroll
        for (int m = 0; m < 4; m++) {
            int c2 = (q - 2)*4 + m;
            float wr = (ar[m]*tr_r + ai[m]*tr_i)*invd;
            float wi = (ai[m]*tr_r - ar[m]*tr_i)*invd;
            g_wsmat[(size_t)bf*64 + i*8 + c2] = make_float2(wr, wi);
        }
    }
}

// ---------------- attention MLP -> e[b,c]. 64 blocks x 320 threads --------
__global__ __launch_bounds__(An) void k_att(const float* __restrict__ mlp_w,
                                            const float* __restrict__ mlp_b,
                                            const float* __restrict__ gvw,
                                            const float* __restrict__ gvb) {
    __shared__ float feat[Fn];
    __shared__ float red[10];
    int b = blockIdx.x >> 3, c = blockIdx.x & 7;
    int tid = threadIdx.x;

    if (tid < Fn) feat[tid] = g_feat[(b*Cn + c)*Fn + tid];
    __syncthreads();

    float dot = 0.f;
    for (int f = 0; f < Fn; f++) dot += feat[f] * mlp_w[f*An + tid];
    float h = tanhf(dot + mlp_b[tid]);
    float part = h * gvw[tid];

    #pragma unroll
    for (int o = 16; o; o >>= 1) part += __shfl_xor_sync(0xffffffffu, part, o);
    int w = tid >> 5, lane = tid & 31;
    if (lane == 0) red[w] = part;
    __syncthreads();
    if (tid == 0) {
        float s = 0.f;
        #pragma unroll
        for (int k = 0; k < 10; k++) s += red[k];
        g_eval[blockIdx.x] = s + gvb[0];
    }
}

// ---------------- beamforming (softmax + ws_mat contraction inline) --------------
// Batched loads: all 32 LDGs of a 2-t group issued before any FMA.
#define TCH 8
__global__ __launch_bounds__(288) void k_beam(const float* __restrict__ dr,
                                              const float* __restrict__ di,
                                              float2* __restrict__ out) {
    int blk = blockIdx.x;
    int b  = blk / (Tn / TCH);
    int t0 = (blk % (Tn / TCH)) * TCH;
    int f = threadIdx.x;
    if (f >= Fn) return;

    // softmax u (8 values, per-thread)
    float ev[8];
    float mx = -1e30f;
    #pragma unroll
    for (int c = 0; c < 8; c++) { ev[c] = 2.0f * g_eval[b*8 + c]; mx = fmaxf(mx, ev[c]); }
    float su = 0.f;
    #pragma unroll
    for (int c = 0; c < 8; c++) { ev[c] = expf(ev[c] - mx); su += ev[c]; }
    float inv = 1.f / su;
    #pragma unroll
    for (int c = 0; c < 8; c++) ev[c] *= inv;

    // ws[e] = sum_c ws_mat[e][c] * u[c]   (float4 loads, 2 complex per load)
    float wr[8], wi[8];
    #pragma unroll
    for (int e = 0; e < 8; e++) { wr[e] = 0.f; wi[e] = 0.f; }
    const float4* wm = (const float4*)(g_wsmat + ((size_t)(b*Fn + f))*64);
    #pragma unroll
    for (int k = 0; k < 32; k++) {
        float4 v = wm[k];
        int e = k >> 2, c0 = (k & 3)*2;
        wr[e] += v.x*ev[c0] + v.z*ev[c0+1];
        wi[e] += v.y*ev[c0] + v.w*ev[c0+1];
    }

    #pragma unroll
    for (int tp = 0; tp < TCH; tp += 2) {
        float xr[2][8], xi[2][8];
        // load phase: 32 independent LDGs in flight
        #pragma unroll
        for (int u = 0; u < 2; u++) {
            size_t base = ((size_t)(b*Tn + t0 + tp + u))*Cn*Fn + f;
            #pragma unroll
            for (int c = 0; c < 8; c++) {
                xr[u][c] = dr[base + (size_t)c*Fn];
                xi[u][c] = di[base + (size_t)c*Fn];
            }
        }
        // compute phase: conj(ws) * x
        #pragma unroll
        for (int u = 0; u < 2; u++) {
            float accr = 0.f, acci = 0.f;
            #pragma unroll
            for (int c = 0; c < 8; c++) {
                accr += wr[c]*xr[u][c] + wi[c]*xi[u][c];
                acci += wr[c]*xi[u][c] - wi[c]*xr[u][c];
            }
            out[(size_t)(b*Tn + t0 + tp + u)*Fn + f] = make_float2(accr, acci);
        }
    }
}

// ---------------- launcher ----------------
extern "C" void kernel_launch(void* const* d_in, const int* in_sizes, int n_in,
                              void* d_out, int out_size) {
    const float* dr    = (const float*)d_in[0];
    const float* di    = (const float*)d_in[1];
    const float* ms    = (const float*)d_in[2];
    const float* mn    = (const float*)d_in[3];
    const float* mlp_w = (const float*)d_in[4];
    const float* mlp_b = (const float*)d_in[5];
    const float* gvw   = (const float*)d_in[6];
    const float* gvb   = (const float*)d_in[7];
    (void)in_sizes; (void)n_in; (void)out_size;

    static bool attr_set = false;
    if (!attr_set) {
        cudaFuncSetAttribute(k_psd_part, cudaFuncAttributeMaxDynamicSharedMemorySize,
                             (int)PSD_SMEM_BYTES);
        attr_set = true;
    }

    k_psd_part<<<dim3((Fn + FT - 1)/FT, TSN, Bn), 256, PSD_SMEM_BYTES>>>(dr, di, ms, mn);
    k_final<<<257, 256>>>();
    k_att<<<Bn*Cn, An>>>(mlp_w, mlp_b, gvw, gvb);
    k_beam<<<Bn*(Tn/TCH), 288>>>(dr, di, (float2*)d_out);
}